// round 1
// baseline (speedup 1.0000x reference)
#include <cuda_runtime.h>
#include <math.h>

// ---------------- problem constants ----------------
#define QL 1024
#define BB 2
#define NH 16
#define DH 64
#define DM 1024
#define DI 4096
#define RL 2048
#define M2 (QL*BB)      // 2048 rows (i*B+b)
#define MR (RL*BB)      // 4096 rows
#define ATT_SCALE 0.125f // 1/sqrt(64)

// ---------------- scratch (static device memory; no allocations) ----------------
__device__ float g_q   [M2*DM];
__device__ float g_k   [M2*DM];
__device__ float g_v   [M2*DM];
__device__ float g_kr  [MR*DM];
__device__ float g_woT [DM*DM];
__device__ float g_ef  [M2*NH*2];
__device__ float g_bk  [M2*NH];
__device__ float g_bkr [MR*NH];
__device__ float g_S   [(size_t)BB*NH*QL*QL];   // 134 MB  scores/probs
__device__ float g_BD  [(size_t)BB*NH*QL*RL];   // 268 MB  raw bd
__device__ float g_attn[M2*DM];
__device__ float g_o   [M2*DM];
__device__ float g_y   [M2*DM];
__device__ float g_t   [M2*DI];
__device__ float g_z   [M2*DM];

// ---------------- generic SGEMM: C[M,N] = A[M,K] @ W[K,N] (+epilogue) ----------------
// M = gridDim.y*128, N = gridDim.x*128, K % 8 == 0. All exact multiples here.
// EPI: 0 none, 1 +bias, 2 +bias then exact GELU
template<int EPI>
__global__ void __launch_bounds__(256) sgemm128(
    const float* __restrict__ A, const float* __restrict__ W,
    const float* __restrict__ bias, float* __restrict__ C,
    int K, int lda, int ldw, int ldc)
{
    __shared__ float As[8][132];   // [k][m], padded: conflict-free stores/loads
    __shared__ float Ws[8][128];   // [k][n]
    const int tid = threadIdx.x;
    const int m0 = blockIdx.y * 128, n0 = blockIdx.x * 128;
    const int tx = tid & 15, ty = tid >> 4;
    float acc[8][8] = {};
    for (int k0 = 0; k0 < K; k0 += 8) {
#pragma unroll
        for (int p = 0; p < 4; p++) {
            int e = p*256 + tid;
            As[e & 7][e >> 3] = A[(size_t)(m0 + (e >> 3))*lda + (k0 + (e & 7))];
        }
#pragma unroll
        for (int p = 0; p < 4; p++) {
            int e = p*256 + tid;
            Ws[e >> 7][e & 127] = W[(size_t)(k0 + (e >> 7))*ldw + (n0 + (e & 127))];
        }
        __syncthreads();
#pragma unroll
        for (int kk = 0; kk < 8; kk++) {
            float a[8], b[8];
#pragma unroll
            for (int i = 0; i < 8; i++) a[i] = As[kk][ty*8 + i];
#pragma unroll
            for (int j = 0; j < 8; j++) b[j] = Ws[kk][tx*8 + j];
#pragma unroll
            for (int i = 0; i < 8; i++)
#pragma unroll
                for (int j = 0; j < 8; j++) acc[i][j] = fmaf(a[i], b[j], acc[i][j]);
        }
        __syncthreads();
    }
#pragma unroll
    for (int i = 0; i < 8; i++) {
        int m = m0 + ty*8 + i;
#pragma unroll
        for (int j = 0; j < 8; j++) {
            int n = n0 + tx*8 + j;
            float c = acc[i][j];
            if (EPI >= 1) c += bias[n];
            if (EPI == 2) c = 0.5f * c * (1.0f + erff(c * 0.7071067811865476f));
            C[(size_t)m*ldc + n] = c;
        }
    }
}

// ---------------- batched NT score GEMM: C[bn][i][j] = sum_d Q[i,b,n,d]*Km[j,b,n,d] ----------------
// Q rows stride 2048 (layout [(i*2+b)*1024 + n*64 + d]); same for Km. K fixed = 64.
__global__ void __launch_bounds__(64) score_nt(
    const float* __restrict__ Q, const float* __restrict__ Km,
    float* __restrict__ C, int Ncols)
{
    __shared__ float Qs[64][65];   // [i][d]
    __shared__ float Ks[64][65];   // [j][d]
    const int bn = blockIdx.z, b = bn >> 4, n = bn & 15;
    const int i0 = blockIdx.y * 64, j0 = blockIdx.x * 64;
    const int tid = threadIdx.x;            // 64 threads
    const float* Qb = Q  + b*DM + n*DH;
    const float* Kb = Km + b*DM + n*DH;
#pragma unroll 8
    for (int p = 0; p < 64; p++) {
        Qs[p][tid] = Qb[(size_t)(i0 + p)*M2 + tid];
        Ks[p][tid] = Kb[(size_t)(j0 + p)*M2 + tid];
    }
    __syncthreads();
    const int tx = tid & 7, ty = tid >> 3;  // 8x8 threads, 8x8 microtile
    float acc[8][8] = {};
#pragma unroll 8
    for (int d = 0; d < 64; d++) {
        float a[8], bb[8];
#pragma unroll
        for (int ii = 0; ii < 8; ii++) a[ii]  = Qs[ty*8 + ii][d];
#pragma unroll
        for (int jj = 0; jj < 8; jj++) bb[jj] = Ks[tx*8 + jj][d];
#pragma unroll
        for (int ii = 0; ii < 8; ii++)
#pragma unroll
            for (int jj = 0; jj < 8; jj++) acc[ii][jj] = fmaf(a[ii], bb[jj], acc[ii][jj]);
    }
    float* Cb = C + (size_t)bn * QL * Ncols;
#pragma unroll
    for (int ii = 0; ii < 8; ii++)
#pragma unroll
        for (int jj = 0; jj < 8; jj++)
            Cb[(size_t)(i0 + ty*8 + ii)*Ncols + (j0 + tx*8 + jj)] = acc[ii][jj];
}

// ---------------- combine: S = (ac + bk + bd_shift + bkr + ef)*SCALE - 1e30*mask ----------------
__global__ void combine_kernel(
    float* __restrict__ S, const float* __restrict__ BD,
    const float* __restrict__ bk, const float* __restrict__ bkr,
    const float* __restrict__ ef, const float* __restrict__ seg_mat,
    const float* __restrict__ mask)
{
    const int bn = blockIdx.z, b = bn >> 4, n = bn & 15;
    const int i = blockIdx.y;
    const int j = blockIdx.x * blockDim.x + threadIdx.x;
    const size_t sidx = ((size_t)bn << 20) + ((size_t)i << 10) + j;
    float s = S[sidx];
    s += bk[((j << 1) + b)*NH + n];
    const int jr = QL + j - i;                       // rel_shift gather (1..2047)
    s += BD[((size_t)bn << 21) + ((size_t)i << 11) + jr];
    s += bkr[((jr << 1) + b)*NH + n];
    const float* e = ef + (((size_t)(i*BB + b))*NH + n)*2;
    const size_t smi = ((((size_t)i << 10) + j)*BB + b)*2;
    s += seg_mat[smi] * e[0] + seg_mat[smi + 1] * e[1];
    s = s * ATT_SCALE - 1e30f * mask[(((size_t)i << 10) + j)*BB + b];
    S[sidx] = s;
}

// ---------------- row softmax over j (in place), 256 threads, 1024 cols ----------------
__global__ void __launch_bounds__(256) softmax_row(float* __restrict__ S)
{
    __shared__ float red[8];
    const size_t base = (size_t)blockIdx.x << 10;
    const int t = threadIdx.x, lane = t & 31, w = t >> 5;
    float v[4];
#pragma unroll
    for (int p = 0; p < 4; p++) v[p] = S[base + t + p*256];
    float m = fmaxf(fmaxf(v[0], v[1]), fmaxf(v[2], v[3]));
#pragma unroll
    for (int o = 16; o; o >>= 1) m = fmaxf(m, __shfl_xor_sync(0xffffffffu, m, o));
    if (!lane) red[w] = m;
    __syncthreads();
    m = red[lane & 7];
#pragma unroll
    for (int o = 4; o; o >>= 1) m = fmaxf(m, __shfl_xor_sync(0xffffffffu, m, o));
    float sum = 0.f;
#pragma unroll
    for (int p = 0; p < 4; p++) { v[p] = expf(v[p] - m); sum += v[p]; }
#pragma unroll
    for (int o = 16; o; o >>= 1) sum += __shfl_xor_sync(0xffffffffu, sum, o);
    __syncthreads();
    if (!lane) red[w] = sum;
    __syncthreads();
    sum = red[lane & 7];
#pragma unroll
    for (int o = 4; o; o >>= 1) sum += __shfl_xor_sync(0xffffffffu, sum, o);
    const float inv = 1.0f / sum;
#pragma unroll
    for (int p = 0; p < 4; p++) S[base + t + p*256] = v[p] * inv;
}

// ---------------- batched P@V: O[i,b,n,d] = sum_j P[bn][i][j] * V[j,b,n,d] ----------------
__global__ void __launch_bounds__(256) pv_gemm(
    const float* __restrict__ P, const float* __restrict__ V, float* __restrict__ O)
{
    __shared__ float Ps[64][17];   // [i][j-chunk]
    __shared__ float Vs[16][65];   // [j][d]
    const int bn = blockIdx.z, b = bn >> 4, n = bn & 15;
    const int i0 = blockIdx.y * 64;
    const float* Pb = P + ((size_t)bn << 20);
    const float* Vb = V + b*DM + n*DH;
    const int tid = threadIdx.x, tx = tid & 15, ty = tid >> 4;
    float acc[4][4] = {};
    for (int k0 = 0; k0 < QL; k0 += 16) {
#pragma unroll
        for (int p = 0; p < 4; p++) {
            int e = p*256 + tid;
            Ps[e >> 4][e & 15] = Pb[(size_t)(i0 + (e >> 4))*QL + (k0 + (e & 15))];
        }
#pragma unroll
        for (int p = 0; p < 4; p++) {
            int e = p*256 + tid;
            Vs[e >> 6][e & 63] = Vb[(size_t)(k0 + (e >> 6))*M2 + (e & 63)];
        }
        __syncthreads();
#pragma unroll
        for (int j = 0; j < 16; j++) {
            float a[4], bb[4];
#pragma unroll
            for (int ii = 0; ii < 4; ii++) a[ii]  = Ps[ty*4 + ii][j];
#pragma unroll
            for (int jj = 0; jj < 4; jj++) bb[jj] = Vs[j][tx*4 + jj];
#pragma unroll
            for (int ii = 0; ii < 4; ii++)
#pragma unroll
                for (int jj = 0; jj < 4; jj++) acc[ii][jj] = fmaf(a[ii], bb[jj], acc[ii][jj]);
        }
        __syncthreads();
    }
#pragma unroll
    for (int ii = 0; ii < 4; ii++)
#pragma unroll
        for (int jj = 0; jj < 4; jj++)
            O[(size_t)(i0 + ty*4 + ii)*M2 + b*DM + n*DH + tx*4 + jj] = acc[ii][jj];
}

// ---------------- small helpers ----------------
// out[row*16+n] = sum_d bias[n*64+d] * X[row*1024 + n*64 + d]
__global__ void bias_dot(const float* __restrict__ X, const float* __restrict__ bias,
                         float* __restrict__ out, int rows)
{
    const int gw = (blockIdx.x * blockDim.x + threadIdx.x) >> 5;
    const int lane = threadIdx.x & 31;
    if (gw >= rows * NH) return;
    const int row = gw >> 4, n = gw & 15;
    float s = bias[n*DH + lane]      * X[(size_t)row*DM + n*DH + lane]
            + bias[n*DH + 32 + lane] * X[(size_t)row*DM + n*DH + 32 + lane];
#pragma unroll
    for (int o = 16; o; o >>= 1) s += __shfl_xor_sync(0xffffffffu, s, o);
    if (!lane) out[gw] = s;
}

// ef[row][n][s] = sum_d (q[row,n,d] + rsb[n,d]) * seg_embed[s,n,d]
__global__ void ef_kernel(const float* __restrict__ q, const float* __restrict__ rsb,
                          const float* __restrict__ se, float* __restrict__ ef)
{
    const int gw = (blockIdx.x * blockDim.x + threadIdx.x) >> 5;
    const int lane = threadIdx.x & 31;
    if (gw >= M2 * NH) return;
    const int row = gw >> 4, n = gw & 15;
    const float v0 = q[(size_t)row*DM + n*DH + lane]      + rsb[n*DH + lane];
    const float v1 = q[(size_t)row*DM + n*DH + 32 + lane] + rsb[n*DH + 32 + lane];
    float s0 = v0*se[n*DH + lane] + v1*se[n*DH + 32 + lane];
    float s1 = v0*se[NH*DH + n*DH + lane] + v1*se[NH*DH + n*DH + 32 + lane];
#pragma unroll
    for (int o = 16; o; o >>= 1) {
        s0 += __shfl_xor_sync(0xffffffffu, s0, o);
        s1 += __shfl_xor_sync(0xffffffffu, s1, o);
    }
    if (!lane) { ef[gw*2] = s0; ef[gw*2 + 1] = s1; }
}

// residual + LayerNorm: out = LN(a + x) * gamma + beta, 1024 cols/row
__global__ void __launch_bounds__(256) add_ln(
    const float* __restrict__ a, const float* __restrict__ x,
    const float* __restrict__ gamma, const float* __restrict__ beta,
    float* __restrict__ out)
{
    __shared__ float buf[1024];
    __shared__ float red[8];
    __shared__ float s_stat;
    const size_t base = (size_t)blockIdx.x << 10;
    const int t = threadIdx.x, lane = t & 31, w = t >> 5;
    float sum = 0.f;
#pragma unroll
    for (int p = 0; p < 4; p++) {
        float v = a[base + t + p*256] + x[base + t + p*256];
        buf[t + p*256] = v; sum += v;
    }
#pragma unroll
    for (int o = 16; o; o >>= 1) sum += __shfl_xor_sync(0xffffffffu, sum, o);
    if (!lane) red[w] = sum;
    __syncthreads();
    if (t == 0) { float s = 0; for (int i = 0; i < 8; i++) s += red[i]; s_stat = s * (1.0f/1024.0f); }
    __syncthreads();
    const float mean = s_stat;
    float vs = 0.f;
#pragma unroll
    for (int p = 0; p < 4; p++) { float d = buf[t + p*256] - mean; vs += d*d; }
#pragma unroll
    for (int o = 16; o; o >>= 1) vs += __shfl_xor_sync(0xffffffffu, vs, o);
    __syncthreads();
    if (!lane) red[w] = vs;
    __syncthreads();
    if (t == 0) { float s = 0; for (int i = 0; i < 8; i++) s += red[i]; s_stat = s * (1.0f/1024.0f); }
    __syncthreads();
    const float r = rsqrtf(s_stat + 1e-12f);
#pragma unroll
    for (int p = 0; p < 4; p++) {
        int c = t + p*256;
        out[base + c] = (buf[c] - mean) * r * gamma[c] + beta[c];
    }
}

// wo [h][nd] -> woT [nd][h]
__global__ void transpose1024(const float* __restrict__ in, float* __restrict__ out)
{
    __shared__ float tile[32][33];
    const int x0 = blockIdx.x * 32, y0 = blockIdx.y * 32;
    const int tx = threadIdx.x, ty = threadIdx.y;
#pragma unroll
    for (int p = 0; p < 4; p++)
        tile[ty + p*8][tx] = in[(size_t)(y0 + ty + p*8)*DM + x0 + tx];
    __syncthreads();
#pragma unroll
    for (int p = 0; p < 4; p++)
        out[(size_t)(x0 + ty + p*8)*DM + y0 + tx] = tile[tx][ty + p*8];
}

// ---------------- host orchestration ----------------
static void run_stream(const float* x, const float* mask, const float* seg_mat,
                       const float* wq, const float* rsb, const float* se,
                       const float* lnga, const float* lnba,
                       const float* w1, const float* b1,
                       const float* w2, const float* b2,
                       const float* lngf, const float* lnbf,
                       float* outp,
                       float* q, float* k, float* v, float* kr, float* woT,
                       float* ef, float* bk, float* bkr, float* S, float* BD,
                       float* attn, float* o, float* y, float* t, float* z)
{
    // q projection
    sgemm128<0><<<dim3(DM/128, M2/128), 256>>>(x, wq, nullptr, q, DM, DM, DM, DM);
    // ef (segment) terms
    ef_kernel<<<(M2*NH*32 + 255)/256, 256>>>(q, rsb, se, ef);
    // ac = q.kT  -> S ; bd = q.krT -> BD
    score_nt<<<dim3(QL/64, QL/64, BB*NH), 64>>>(q, k,  S,  QL);
    score_nt<<<dim3(RL/64, QL/64, BB*NH), 64>>>(q, kr, BD, RL);
    // combine + scale + mask
    combine_kernel<<<dim3(QL/256, QL, BB*NH), 256>>>(S, BD, bk, bkr, ef, seg_mat, mask);
    // softmax over j
    softmax_row<<<BB*NH*QL, 256>>>(S);
    // attn = P @ V
    pv_gemm<<<dim3(1, QL/64, BB*NH), 256>>>(S, v, attn);
    // o = attn @ woT ; y = LN(o + x)
    sgemm128<0><<<dim3(DM/128, M2/128), 256>>>(attn, woT, nullptr, o, DM, DM, DM, DM);
    add_ln<<<M2, 256>>>(o, x, lnga, lnba, y);
    // FFN
    sgemm128<2><<<dim3(DI/128, M2/128), 256>>>(y, w1, b1, t, DM, DM, DI, DI);
    sgemm128<1><<<dim3(DM/128, M2/128), 256>>>(t, w2, b2, z, DI, DI, DM, DM);
    add_ln<<<M2, 256>>>(z, y, lngf, lnbf, outp);
}

extern "C" void kernel_launch(void* const* d_in, const int* in_sizes, int n_in,
                              void* d_out, int out_size)
{
    (void)in_sizes; (void)n_in; (void)out_size;
    const float* h       = (const float*)d_in[0];
    const float* g       = (const float*)d_in[1];
    const float* r       = (const float*)d_in[2];
    const float* mask_h  = (const float*)d_in[3];
    const float* mask_g  = (const float*)d_in[4];
    const float* seg_mat = (const float*)d_in[5];
    const float* wq      = (const float*)d_in[6];
    const float* wk      = (const float*)d_in[7];
    const float* wv      = (const float*)d_in[8];
    const float* wo      = (const float*)d_in[9];
    const float* wr      = (const float*)d_in[10];
    const float* rwb     = (const float*)d_in[11];
    const float* rrb     = (const float*)d_in[12];
    const float* rsb     = (const float*)d_in[13];
    const float* se      = (const float*)d_in[14];
    const float* lnga    = (const float*)d_in[15];
    const float* lnba    = (const float*)d_in[16];
    const float* w1      = (const float*)d_in[17];
    const float* b1      = (const float*)d_in[18];
    const float* w2      = (const float*)d_in[19];
    const float* b2      = (const float*)d_in[20];
    const float* lngf    = (const float*)d_in[21];
    const float* lnbf    = (const float*)d_in[22];

    float *q,*k,*v,*kr,*woT,*ef,*bk,*bkr,*S,*BD,*attn,*o,*y,*t,*z;
    cudaGetSymbolAddress((void**)&q,    g_q);
    cudaGetSymbolAddress((void**)&k,    g_k);
    cudaGetSymbolAddress((void**)&v,    g_v);
    cudaGetSymbolAddress((void**)&kr,   g_kr);
    cudaGetSymbolAddress((void**)&woT,  g_woT);
    cudaGetSymbolAddress((void**)&ef,   g_ef);
    cudaGetSymbolAddress((void**)&bk,   g_bk);
    cudaGetSymbolAddress((void**)&bkr,  g_bkr);
    cudaGetSymbolAddress((void**)&S,    g_S);
    cudaGetSymbolAddress((void**)&BD,   g_BD);
    cudaGetSymbolAddress((void**)&attn, g_attn);
    cudaGetSymbolAddress((void**)&o,    g_o);
    cudaGetSymbolAddress((void**)&y,    g_y);
    cudaGetSymbolAddress((void**)&t,    g_t);
    cudaGetSymbolAddress((void**)&z,    g_z);

    // shared precomputation
    transpose1024<<<dim3(32, 32), dim3(32, 8)>>>(wo, woT);
    sgemm128<0><<<dim3(DM/128, M2/128), 256>>>(h, wk, nullptr, k,  DM, DM, DM, DM);
    sgemm128<0><<<dim3(DM/128, M2/128), 256>>>(h, wv, nullptr, v,  DM, DM, DM, DM);
    sgemm128<0><<<dim3(DM/128, MR/128), 256>>>(r, wr, nullptr, kr, DM, DM, DM, DM);
    bias_dot<<<(M2*NH*32 + 255)/256, 256>>>(k,  rwb, bk,  M2);
    bias_dot<<<(MR*NH*32 + 255)/256, 256>>>(kr, rrb, bkr, MR);

    float* out_h = (float*)d_out;
    float* out_g = out_h + (size_t)M2*DM;

    // content stream (h, causal-excl-self mask)
    run_stream(h, mask_h, seg_mat, wq, rsb, se, lnga, lnba,
               w1, b1, w2, b2, lngf, lnbf, out_h,
               q, k, v, kr, woT, ef, bk, bkr, S, BD, attn, o, y, t, z);
    // query stream (g, causal-incl-self mask)
    run_stream(g, mask_g, seg_mat, wq, rsb, se, lnga, lnba,
               w1, b1, w2, b2, lngf, lnbf, out_g,
               q, k, v, kr, woT, ef, bk, bkr, S, BD, attn, o, y, t, z);
}

// round 3
// speedup vs baseline: 2.0201x; 2.0201x over previous
#include <cuda_runtime.h>
#include <cuda_bf16.h>
#include <math.h>
#include <stdint.h>

// ---------------- problem constants ----------------
#define QL 1024
#define BB 2
#define NH 16
#define DH 64
#define DM 1024
#define DI 4096
#define RL 2048
#define M2 (QL*BB)      // 2048 rows (i*B+b)
#define MR (RL*BB)      // 4096 rows
#define ATT_SCALE 0.125f

// ================= low-level helpers (all baseline PTX, sm_80+) =================
__device__ __forceinline__ uint32_t smem_u32(const void* p) {
    uint32_t a;
    asm("{ .reg .u64 t; cvta.to.shared.u64 t, %1; cvt.u32.u64 %0, t; }" : "=r"(a) : "l"(p));
    return a;
}
__device__ __forceinline__ void cp16(uint32_t dst, const void* src) {
    asm volatile("cp.async.cg.shared.global [%0], [%1], 16;" :: "r"(dst), "l"(src));
}
__device__ __forceinline__ void cp_commit() {
    asm volatile("cp.async.commit_group;" ::: "memory");
}
__device__ __forceinline__ void ldsm4(uint32_t (&r)[4], uint32_t addr) {
    asm volatile("ldmatrix.sync.aligned.m8n8.x4.shared.b16 {%0,%1,%2,%3}, [%4];"
        : "=r"(r[0]), "=r"(r[1]), "=r"(r[2]), "=r"(r[3]) : "r"(addr));
}
__device__ __forceinline__ void mma16816(float (&d)[4], const uint32_t (&a)[4],
                                         uint32_t b0, uint32_t b1) {
    asm volatile("mma.sync.aligned.m16n8k16.row.col.f32.bf16.bf16.f32 "
        "{%0,%1,%2,%3},{%4,%5,%6,%7},{%8,%9},{%0,%1,%2,%3};"
        : "+f"(d[0]), "+f"(d[1]), "+f"(d[2]), "+f"(d[3])
        : "r"(a[0]), "r"(a[1]), "r"(a[2]), "r"(a[3]), "r"(b0), "r"(b1));
}

// ---------------- scratch (static device memory; no allocations) ----------------
__device__ float g_q   [M2*DM];
__device__ float g_q2  [M2*DM];
__device__ float g_k   [M2*DM];
__device__ float g_v   [M2*DM];
__device__ float g_kr  [MR*DM];
__device__ float g_ef  [M2*NH*2];
__device__ float g_bk  [M2*NH];
__device__ float g_bkr [MR*NH];
__device__ float g_S   [(size_t)BB*NH*QL*QL];
__device__ float g_BD  [(size_t)BB*NH*QL*RL];
__device__ float g_attn[M2*DM];
__device__ float g_o   [M2*DM];
__device__ float g_y   [M2*DM];
__device__ float g_t   [M2*DI];
__device__ float g_z   [M2*DM];
// bf16 split buffers (256B aligned for 16B vector access)
__device__ __align__(256) __nv_bfloat16 g_Ah [M2*DI];
__device__ __align__(256) __nv_bfloat16 g_Al [M2*DI];
__device__ __align__(256) __nv_bfloat16 g_wqT[2*DM*DM];   // [hi | lo], layout [N][K]
__device__ __align__(256) __nv_bfloat16 g_wkT[2*DM*DM];
__device__ __align__(256) __nv_bfloat16 g_wvT[2*DM*DM];
__device__ __align__(256) __nv_bfloat16 g_wrT[2*DM*DM];
__device__ __align__(256) __nv_bfloat16 g_woC[2*DM*DM];
__device__ __align__(256) __nv_bfloat16 g_w1T[2*DM*DI];
__device__ __align__(256) __nv_bfloat16 g_w2T[2*DI*DM];

// ================= conversion kernels =================
// straight split: X fp32 [n] -> hi/lo bf16 same layout (n % 4 == 0)
__global__ void conv_split(const float* __restrict__ X, __nv_bfloat16* __restrict__ hi,
                           __nv_bfloat16* __restrict__ lo, int n4)
{
    int i = blockIdx.x * blockDim.x + threadIdx.x;
    if (i >= n4) return;
    float4 v = ((const float4*)X)[i];
    __nv_bfloat16 hx = __float2bfloat16(v.x), hy = __float2bfloat16(v.y);
    __nv_bfloat16 hz = __float2bfloat16(v.z), hw = __float2bfloat16(v.w);
    __nv_bfloat16 lx = __float2bfloat16(v.x - __bfloat162float(hx));
    __nv_bfloat16 ly = __float2bfloat16(v.y - __bfloat162float(hy));
    __nv_bfloat16 lz = __float2bfloat16(v.z - __bfloat162float(hz));
    __nv_bfloat16 lw = __float2bfloat16(v.w - __bfloat162float(hw));
    ((__nv_bfloat162*)hi)[2*i]   = __nv_bfloat162(hx, hy);
    ((__nv_bfloat162*)hi)[2*i+1] = __nv_bfloat162(hz, hw);
    ((__nv_bfloat162*)lo)[2*i]   = __nv_bfloat162(lx, ly);
    ((__nv_bfloat162*)lo)[2*i+1] = __nv_bfloat162(lz, lw);
}

// transpose split: W fp32 [K,N] -> hi/lo bf16 [N,K]
__global__ void convT_split(const float* __restrict__ W, __nv_bfloat16* __restrict__ hi,
                            __nv_bfloat16* __restrict__ lo, int K, int N)
{
    __shared__ float t[32][33];
    int k0 = blockIdx.y * 32, n0 = blockIdx.x * 32;
    int tx = threadIdx.x, ty = threadIdx.y;
#pragma unroll
    for (int p = 0; p < 4; p++)
        t[ty + p*8][tx] = W[(size_t)(k0 + ty + p*8)*N + n0 + tx];
    __syncthreads();
#pragma unroll
    for (int p = 0; p < 4; p++) {
        float v = t[tx][ty + p*8];
        __nv_bfloat16 h = __float2bfloat16(v);
        size_t o = (size_t)(n0 + ty + p*8)*K + k0 + tx;
        hi[o] = h;
        lo[o] = __float2bfloat16(v - __bfloat162float(h));
    }
}

// ================= split-bf16 GEMM via mma.sync (HMMA tensor path) =================
// C[M,N] = A[M,K] @ B^T, B stored [N,K]; A/B as hi/lo bf16 pairs.
// Block 128x128, K-chunk 64, 2-stage cp.async pipeline, SW128-swizzled SMEM,
// ldmatrix fragment loads. EPI: 0 none, 1 +bias, 2 +bias+exact GELU.
#define GSTAGE 65536
#define GSMEM_BYTES (2*GSTAGE)

__device__ __forceinline__ void g_load_stage(
    const __nv_bfloat16* __restrict__ Ah, const __nv_bfloat16* __restrict__ Al,
    const __nv_bfloat16* __restrict__ Bh, const __nv_bfloat16* __restrict__ Bl,
    uint32_t st, int m0, int n0, int K, int kc, int tid)
{
    const size_t ko = (size_t)kc * 64;
#pragma unroll
    for (int p = 0; p < 4; p++) {
        int c = p*256 + tid;                 // 0..1023 16B-chunks per tile
        int row = c >> 3, kcol = c & 7;
        uint32_t off = row*128 + kcol*16;
        uint32_t sw = off ^ ((row & 7) << 4);
        const size_t ga = (size_t)(m0 + row)*K + ko + kcol*8;
        const size_t gb = (size_t)(n0 + row)*K + ko + kcol*8;
        cp16(st + sw,         Ah + ga);
        cp16(st + 16384 + sw, Al + ga);
        cp16(st + 32768 + sw, Bh + gb);
        cp16(st + 49152 + sw, Bl + gb);
    }
    cp_commit();
}

template<int EPI>
__global__ void __launch_bounds__(256, 1) gemm_mma(
    const __nv_bfloat16* __restrict__ Ah, const __nv_bfloat16* __restrict__ Al,
    const __nv_bfloat16* __restrict__ Bh, const __nv_bfloat16* __restrict__ Bl,
    const float* __restrict__ bias, float* __restrict__ C, int K, int ldc)
{
    extern __shared__ char dsm[];
    const uint32_t sbase = smem_u32(dsm);
    const int tid = threadIdx.x, lane = tid & 31, warp = tid >> 5;
    const int m0 = blockIdx.y * 128, n0 = blockIdx.x * 128;
    const int wm = (warp & 1) * 64, wn = (warp >> 1) * 32;
    const int NC = K >> 6;

    float acc[4][4][4] = {};   // [im][in][reg]

    g_load_stage(Ah, Al, Bh, Bl, sbase,          m0, n0, K, 0, tid);
    g_load_stage(Ah, Al, Bh, Bl, sbase + GSTAGE, m0, n0, K, 1, tid);
    asm volatile("cp.async.wait_group 1;" ::: "memory");
    __syncthreads();

    // precomputed per-lane fragment address offsets (within a stage tile)
    // A: row = wm + im*16 + (lane&15), kbyte = ks*32 + (lane&16)
    // B: row = wn + np*16 + ((lane&16)>>1) + (lane&7), kbyte = ks*32 + ((lane&8)<<1)
    const int arow = wm + (lane & 15);
    const int akb  = (lane & 16);
    const int brow = wn + ((lane & 16) >> 1) + (lane & 7);
    const int bkb  = ((lane & 8) << 1);

    for (int kc = 0; kc < NC; kc++) {
        const uint32_t st = sbase + (kc & 1) * GSTAGE;
#pragma unroll
        for (int ks = 0; ks < 4; ks++) {
            const int kb = ks*32;
            uint32_t ah[4][4], al[4][4], bh[2][4], bl[2][4];
#pragma unroll
            for (int im = 0; im < 4; im++) {
                int row = arow + im*16;
                uint32_t off = (uint32_t)(row*128 + kb + akb);
                off ^= (row & 7) << 4;
                ldsm4(ah[im], st + off);
                ldsm4(al[im], st + 16384 + off);
            }
#pragma unroll
            for (int np = 0; np < 2; np++) {
                int row = brow + np*16;
                uint32_t off = (uint32_t)(row*128 + kb + bkb);
                off ^= (row & 7) << 4;
                ldsm4(bh[np], st + 32768 + off);
                ldsm4(bl[np], st + 49152 + off);
            }
#pragma unroll
            for (int im = 0; im < 4; im++)
#pragma unroll
                for (int in = 0; in < 4; in++) {
                    const int np = in >> 1, hf = (in & 1) * 2;
                    mma16816(acc[im][in], ah[im], bh[np][hf], bh[np][hf+1]);
                    mma16816(acc[im][in], ah[im], bl[np][hf], bl[np][hf+1]);
                    mma16816(acc[im][in], al[im], bh[np][hf], bh[np][hf+1]);
                }
        }
        __syncthreads();
        if (kc + 2 < NC) {
            g_load_stage(Ah, Al, Bh, Bl, sbase + (kc & 1)*GSTAGE, m0, n0, K, kc + 2, tid);
            asm volatile("cp.async.wait_group 1;" ::: "memory");
        } else {
            asm volatile("cp.async.wait_group 0;" ::: "memory");
        }
        __syncthreads();
    }

    // ---- epilogue ----
    const int rbase = m0 + wm + (lane >> 2);
    const int cbase = n0 + wn + 2*(lane & 3);
#pragma unroll
    for (int im = 0; im < 4; im++) {
#pragma unroll
        for (int in = 0; in < 4; in++) {
            int col = cbase + in*8;
            float v0 = acc[im][in][0], v1 = acc[im][in][1];
            float v2 = acc[im][in][2], v3 = acc[im][in][3];
            if (EPI >= 1) {
                float b0 = bias[col], b1 = bias[col+1];
                v0 += b0; v1 += b1; v2 += b0; v3 += b1;
            }
            if (EPI == 2) {
                v0 = 0.5f*v0*(1.0f + erff(v0*0.7071067811865476f));
                v1 = 0.5f*v1*(1.0f + erff(v1*0.7071067811865476f));
                v2 = 0.5f*v2*(1.0f + erff(v2*0.7071067811865476f));
                v3 = 0.5f*v3*(1.0f + erff(v3*0.7071067811865476f));
            }
            int r0 = rbase + im*16, r1 = r0 + 8;
            *(float2*)(C + (size_t)r0*ldc + col) = make_float2(v0, v1);
            *(float2*)(C + (size_t)r1*ldc + col) = make_float2(v2, v3);
        }
    }
}

// ================= attention kernels (fp32, unchanged from R1) =================
__global__ void __launch_bounds__(64) score_nt(
    const float* __restrict__ Q, const float* __restrict__ Km,
    float* __restrict__ C, int Ncols)
{
    __shared__ float Qs[64][65];
    __shared__ float Ks[64][65];
    const int bn = blockIdx.z, b = bn >> 4, n = bn & 15;
    const int i0 = blockIdx.y * 64, j0 = blockIdx.x * 64;
    const int tid = threadIdx.x;
    const float* Qb = Q  + b*DM + n*DH;
    const float* Kb = Km + b*DM + n*DH;
#pragma unroll 8
    for (int p = 0; p < 64; p++) {
        Qs[p][tid] = Qb[(size_t)(i0 + p)*M2 + tid];
        Ks[p][tid] = Kb[(size_t)(j0 + p)*M2 + tid];
    }
    __syncthreads();
    const int tx = tid & 7, ty = tid >> 3;
    float acc[8][8] = {};
#pragma unroll 8
    for (int d = 0; d < 64; d++) {
        float a[8], bb[8];
#pragma unroll
        for (int ii = 0; ii < 8; ii++) a[ii]  = Qs[ty*8 + ii][d];
#pragma unroll
        for (int jj = 0; jj < 8; jj++) bb[jj] = Ks[tx*8 + jj][d];
#pragma unroll
        for (int ii = 0; ii < 8; ii++)
#pragma unroll
            for (int jj = 0; jj < 8; jj++) acc[ii][jj] = fmaf(a[ii], bb[jj], acc[ii][jj]);
    }
    float* Cb = C + (size_t)bn * QL * Ncols;
#pragma unroll
    for (int ii = 0; ii < 8; ii++)
#pragma unroll
        for (int jj = 0; jj < 8; jj++)
            Cb[(size_t)(i0 + ty*8 + ii)*Ncols + (j0 + tx*8 + jj)] = acc[ii][jj];
}

__global__ void combine_kernel(
    float* __restrict__ S, const float* __restrict__ BD,
    const float* __restrict__ bk, const float* __restrict__ bkr,
    const float* __restrict__ ef, const float* __restrict__ seg_mat,
    const float* __restrict__ mask)
{
    const int bn = blockIdx.z, b = bn >> 4, n = bn & 15;
    const int i = blockIdx.y;
    const int j = blockIdx.x * blockDim.x + threadIdx.x;
    const size_t sidx = ((size_t)bn << 20) + ((size_t)i << 10) + j;
    float s = S[sidx];
    s += bk[((j << 1) + b)*NH + n];
    const int jr = QL + j - i;
    s += BD[((size_t)bn << 21) + ((size_t)i << 11) + jr];
    s += bkr[((jr << 1) + b)*NH + n];
    const float* e = ef + (((size_t)(i*BB + b))*NH + n)*2;
    const size_t smi = ((((size_t)i << 10) + j)*BB + b)*2;
    s += seg_mat[smi] * e[0] + seg_mat[smi + 1] * e[1];
    s = s * ATT_SCALE - 1e30f * mask[(((size_t)i << 10) + j)*BB + b];
    S[sidx] = s;
}

__global__ void __launch_bounds__(256) softmax_row(float* __restrict__ S)
{
    __shared__ float red[8];
    const size_t base = (size_t)blockIdx.x << 10;
    const int t = threadIdx.x, lane = t & 31, w = t >> 5;
    float v[4];
#pragma unroll
    for (int p = 0; p < 4; p++) v[p] = S[base + t + p*256];
    float m = fmaxf(fmaxf(v[0], v[1]), fmaxf(v[2], v[3]));
#pragma unroll
    for (int o = 16; o; o >>= 1) m = fmaxf(m, __shfl_xor_sync(0xffffffffu, m, o));
    if (!lane) red[w] = m;
    __syncthreads();
    m = red[lane & 7];
#pragma unroll
    for (int o = 4; o; o >>= 1) m = fmaxf(m, __shfl_xor_sync(0xffffffffu, m, o));
    float sum = 0.f;
#pragma unroll
    for (int p = 0; p < 4; p++) { v[p] = expf(v[p] - m); sum += v[p]; }
#pragma unroll
    for (int o = 16; o; o >>= 1) sum += __shfl_xor_sync(0xffffffffu, sum, o);
    __syncthreads();
    if (!lane) red[w] = sum;
    __syncthreads();
    sum = red[lane & 7];
#pragma unroll
    for (int o = 4; o; o >>= 1) sum += __shfl_xor_sync(0xffffffffu, sum, o);
    const float inv = 1.0f / sum;
#pragma unroll
    for (int p = 0; p < 4; p++) S[base + t + p*256] = v[p] * inv;
}

__global__ void __launch_bounds__(256) pv_gemm(
    const float* __restrict__ P, const float* __restrict__ V, float* __restrict__ O)
{
    __shared__ float Ps[64][17];
    __shared__ float Vs[16][65];
    const int bn = blockIdx.z, b = bn >> 4, n = bn & 15;
    const int i0 = blockIdx.y * 64;
    const float* Pb = P + ((size_t)bn << 20);
    const float* Vb = V + b*DM + n*DH;
    const int tid = threadIdx.x, tx = tid & 15, ty = tid >> 4;
    float acc[4][4] = {};
    for (int k0 = 0; k0 < QL; k0 += 16) {
#pragma unroll
        for (int p = 0; p < 4; p++) {
            int e = p*256 + tid;
            Ps[e >> 4][e & 15] = Pb[(size_t)(i0 + (e >> 4))*QL + (k0 + (e & 15))];
        }
#pragma unroll
        for (int p = 0; p < 4; p++) {
            int e = p*256 + tid;
            Vs[e >> 6][e & 63] = Vb[(size_t)(k0 + (e >> 6))*M2 + (e & 63)];
        }
        __syncthreads();
#pragma unroll
        for (int j = 0; j < 16; j++) {
            float a[4], bb[4];
#pragma unroll
            for (int ii = 0; ii < 4; ii++) a[ii]  = Ps[ty*4 + ii][j];
#pragma unroll
            for (int jj = 0; jj < 4; jj++) bb[jj] = Vs[j][tx*4 + jj];
#pragma unroll
            for (int ii = 0; ii < 4; ii++)
#pragma unroll
                for (int jj = 0; jj < 4; jj++) acc[ii][jj] = fmaf(a[ii], bb[jj], acc[ii][jj]);
        }
        __syncthreads();
    }
#pragma unroll
    for (int ii = 0; ii < 4; ii++)
#pragma unroll
        for (int jj = 0; jj < 4; jj++)
            O[(size_t)(i0 + ty*4 + ii)*M2 + b*DM + n*DH + tx*4 + jj] = acc[ii][jj];
}

__global__ void bias_dot(const float* __restrict__ X, const float* __restrict__ bias,
                         float* __restrict__ out, int rows)
{
    const int gw = (blockIdx.x * blockDim.x + threadIdx.x) >> 5;
    const int lane = threadIdx.x & 31;
    if (gw >= rows * NH) return;
    const int row = gw >> 4, n = gw & 15;
    float s = bias[n*DH + lane]      * X[(size_t)row*DM + n*DH + lane]
            + bias[n*DH + 32 + lane] * X[(size_t)row*DM + n*DH + 32 + lane];
#pragma unroll
    for (int o = 16; o; o >>= 1) s += __shfl_xor_sync(0xffffffffu, s, o);
    if (!lane) out[gw] = s;
}

__global__ void ef_kernel(const float* __restrict__ q, const float* __restrict__ rsb,
                          const float* __restrict__ se, float* __restrict__ ef)
{
    const int gw = (blockIdx.x * blockDim.x + threadIdx.x) >> 5;
    const int lane = threadIdx.x & 31;
    if (gw >= M2 * NH) return;
    const int row = gw >> 4, n = gw & 15;
    const float v0 = q[(size_t)row*DM + n*DH + lane]      + rsb[n*DH + lane];
    const float v1 = q[(size_t)row*DM + n*DH + 32 + lane] + rsb[n*DH + 32 + lane];
    float s0 = v0*se[n*DH + lane] + v1*se[n*DH + 32 + lane];
    float s1 = v0*se[NH*DH + n*DH + lane] + v1*se[NH*DH + n*DH + 32 + lane];
#pragma unroll
    for (int o = 16; o; o >>= 1) {
        s0 += __shfl_xor_sync(0xffffffffu, s0, o);
        s1 += __shfl_xor_sync(0xffffffffu, s1, o);
    }
    if (!lane) { ef[gw*2] = s0; ef[gw*2 + 1] = s1; }
}

__global__ void __launch_bounds__(256) add_ln(
    const float* __restrict__ a, const float* __restrict__ x,
    const float* __restrict__ gamma, const float* __restrict__ beta,
    float* __restrict__ out)
{
    __shared__ float buf[1024];
    __shared__ float red[8];
    __shared__ float s_stat;
    const size_t base = (size_t)blockIdx.x << 10;
    const int t = threadIdx.x, lane = t & 31, w = t >> 5;
    float sum = 0.f;
#pragma unroll
    for (int p = 0; p < 4; p++) {
        float v = a[base + t + p*256] + x[base + t + p*256];
        buf[t + p*256] = v; sum += v;
    }
#pragma unroll
    for (int o = 16; o; o >>= 1) sum += __shfl_xor_sync(0xffffffffu, sum, o);
    if (!lane) red[w] = sum;
    __syncthreads();
    if (t == 0) { float s = 0; for (int i = 0; i < 8; i++) s += red[i]; s_stat = s * (1.0f/1024.0f); }
    __syncthreads();
    const float mean = s_stat;
    float vs = 0.f;
#pragma unroll
    for (int p = 0; p < 4; p++) { float d = buf[t + p*256] - mean; vs += d*d; }
#pragma unroll
    for (int o = 16; o; o >>= 1) vs += __shfl_xor_sync(0xffffffffu, vs, o);
    __syncthreads();
    if (!lane) red[w] = vs;
    __syncthreads();
    if (t == 0) { float s = 0; for (int i = 0; i < 8; i++) s += red[i]; s_stat = s * (1.0f/1024.0f); }
    __syncthreads();
    const float r = rsqrtf(s_stat + 1e-12f);
#pragma unroll
    for (int p = 0; p < 4; p++) {
        int c = t + p*256;
        out[base + c] = (buf[c] - mean) * r * gamma[c] + beta[c];
    }
}

// ================= host orchestration =================
static void conv(const float* x, __nv_bfloat16* hi, __nv_bfloat16* lo, size_t n)
{
    int n4 = (int)(n / 4);
    conv_split<<<(n4 + 255)/256, 256>>>(x, hi, lo, n4);
}

static void gemm(int epi, const __nv_bfloat16* Ah, const __nv_bfloat16* Al,
                 const __nv_bfloat16* Bpair, const float* bias, float* C,
                 int M, int N, int K)
{
    const __nv_bfloat16* Bh = Bpair;
    const __nv_bfloat16* Bl = Bpair + (size_t)N*K;
    dim3 gr(N/128, M/128);
    if (epi == 0)      gemm_mma<0><<<gr, 256, GSMEM_BYTES>>>(Ah, Al, Bh, Bl, bias, C, K, N);
    else if (epi == 1) gemm_mma<1><<<gr, 256, GSMEM_BYTES>>>(Ah, Al, Bh, Bl, bias, C, K, N);
    else               gemm_mma<2><<<gr, 256, GSMEM_BYTES>>>(Ah, Al, Bh, Bl, bias, C, K, N);
}

extern "C" void kernel_launch(void* const* d_in, const int* in_sizes, int n_in,
                              void* d_out, int out_size)
{
    (void)in_sizes; (void)n_in; (void)out_size;
    const float* h       = (const float*)d_in[0];
    const float* g       = (const float*)d_in[1];
    const float* r       = (const float*)d_in[2];
    const float* mask_h  = (const float*)d_in[3];
    const float* mask_g  = (const float*)d_in[4];
    const float* seg_mat = (const float*)d_in[5];
    const float* wq      = (const float*)d_in[6];
    const float* wk      = (const float*)d_in[7];
    const float* wv      = (const float*)d_in[8];
    const float* wo      = (const float*)d_in[9];
    const float* wr      = (const float*)d_in[10];
    const float* rwb     = (const float*)d_in[11];
    const float* rrb     = (const float*)d_in[12];
    const float* rsb     = (const float*)d_in[13];
    const float* se      = (const float*)d_in[14];
    const float* lnga    = (const float*)d_in[15];
    const float* lnba    = (const float*)d_in[16];
    const float* w1      = (const float*)d_in[17];
    const float* b1      = (const float*)d_in[18];
    const float* w2      = (const float*)d_in[19];
    const float* b2      = (const float*)d_in[20];
    const float* lngf    = (const float*)d_in[21];
    const float* lnbf    = (const float*)d_in[22];

    cudaFuncSetAttribute(gemm_mma<0>, cudaFuncAttributeMaxDynamicSharedMemorySize, GSMEM_BYTES);
    cudaFuncSetAttribute(gemm_mma<1>, cudaFuncAttributeMaxDynamicSharedMemorySize, GSMEM_BYTES);
    cudaFuncSetAttribute(gemm_mma<2>, cudaFuncAttributeMaxDynamicSharedMemorySize, GSMEM_BYTES);

    float *q,*q2,*k,*v,*kr,*ef,*bk,*bkr,*S,*BD,*attn,*o,*y,*t,*z;
    __nv_bfloat16 *Ah,*Al,*wqT,*wkT,*wvT,*wrT,*woC,*w1T,*w2T;
    cudaGetSymbolAddress((void**)&q,    g_q);
    cudaGetSymbolAddress((void**)&q2,   g_q2);
    cudaGetSymbolAddress((void**)&k,    g_k);
    cudaGetSymbolAddress((void**)&v,    g_v);
    cudaGetSymbolAddress((void**)&kr,   g_kr);
    cudaGetSymbolAddress((void**)&ef,   g_ef);
    cudaGetSymbolAddress((void**)&bk,   g_bk);
    cudaGetSymbolAddress((void**)&bkr,  g_bkr);
    cudaGetSymbolAddress((void**)&S,    g_S);
    cudaGetSymbolAddress((void**)&BD,   g_BD);
    cudaGetSymbolAddress((void**)&attn, g_attn);
    cudaGetSymbolAddress((void**)&o,    g_o);
    cudaGetSymbolAddress((void**)&y,    g_y);
    cudaGetSymbolAddress((void**)&t,    g_t);
    cudaGetSymbolAddress((void**)&z,    g_z);
    cudaGetSymbolAddress((void**)&Ah,   g_Ah);
    cudaGetSymbolAddress((void**)&Al,   g_Al);
    cudaGetSymbolAddress((void**)&wqT,  g_wqT);
    cudaGetSymbolAddress((void**)&wkT,  g_wkT);
    cudaGetSymbolAddress((void**)&wvT,  g_wvT);
    cudaGetSymbolAddress((void**)&wrT,  g_wrT);
    cudaGetSymbolAddress((void**)&woC,  g_woC);
    cudaGetSymbolAddress((void**)&w1T,  g_w1T);
    cudaGetSymbolAddress((void**)&w2T,  g_w2T);

    // ---- weight prep: transpose+split to bf16 [N,K] ----
    dim3 tb(32, 8);
    convT_split<<<dim3(DM/32, DM/32), tb>>>(wq, wqT, wqT + (size_t)DM*DM, DM, DM);
    convT_split<<<dim3(DM/32, DM/32), tb>>>(wk, wkT, wkT + (size_t)DM*DM, DM, DM);
    convT_split<<<dim3(DM/32, DM/32), tb>>>(wv, wvT, wvT + (size_t)DM*DM, DM, DM);
    convT_split<<<dim3(DM/32, DM/32), tb>>>(wr, wrT, wrT + (size_t)DM*DM, DM, DM);
    conv(wo, woC, woC + (size_t)DM*DM, (size_t)DM*DM);   // wo[h][nd] is already [N,K]
    convT_split<<<dim3(DI/32, DM/32), tb>>>(w1, w1T, w1T + (size_t)DM*DI, DM, DI);
    convT_split<<<dim3(DM/32, DI/32), tb>>>(w2, w2T, w2T + (size_t)DI*DM, DI, DM);

    // ---- shared projections ----
    conv(h, Ah, Al, (size_t)M2*DM);
    gemm(0, Ah, Al, wkT, nullptr, k,  M2, DM, DM);
    gemm(0, Ah, Al, wvT, nullptr, v,  M2, DM, DM);
    gemm(0, Ah, Al, wqT, nullptr, q,  M2, DM, DM);
    conv(r, Ah, Al, (size_t)MR*DM);
    gemm(0, Ah, Al, wrT, nullptr, kr, MR, DM, DM);
    conv(g, Ah, Al, (size_t)M2*DM);
    gemm(0, Ah, Al, wqT, nullptr, q2, M2, DM, DM);
    bias_dot<<<(M2*NH*32 + 255)/256, 256>>>(k,  rwb, bk,  M2);
    bias_dot<<<(MR*NH*32 + 255)/256, 256>>>(kr, rrb, bkr, MR);

    float* out_h = (float*)d_out;
    float* out_g = out_h + (size_t)M2*DM;

    // ---- two streams ----
    for (int s = 0; s < 2; s++) {
        const float* x    = s ? g : h;
        const float* mask = s ? mask_g : mask_h;
        const float* qs   = s ? q2 : q;
        float* outp       = s ? out_g : out_h;

        ef_kernel<<<(M2*NH*32 + 255)/256, 256>>>(qs, rsb, se, ef);
        score_nt<<<dim3(QL/64, QL/64, BB*NH), 64>>>(qs, k,  S,  QL);
        score_nt<<<dim3(RL/64, QL/64, BB*NH), 64>>>(qs, kr, BD, RL);
        combine_kernel<<<dim3(QL/256, QL, BB*NH), 256>>>(S, BD, bk, bkr, ef, seg_mat, mask);
        softmax_row<<<BB*NH*QL, 256>>>(S);
        pv_gemm<<<dim3(1, QL/64, BB*NH), 256>>>(S, v, attn);

        conv(attn, Ah, Al, (size_t)M2*DM);
        gemm(0, Ah, Al, woC, nullptr, o, M2, DM, DM);
        add_ln<<<M2, 256>>>(o, x, lnga, lnba, y);

        conv(y, Ah, Al, (size_t)M2*DM);
        gemm(2, Ah, Al, w1T, b1, t, M2, DI, DM);
        conv(t, Ah, Al, (size_t)M2*DI);
        gemm(1, Ah, Al, w2T, b2, z, M2, DM, DI);
        add_ln<<<M2, 256>>>(z, y, lngf, lnbf, outp);
    }
}

// round 4
// speedup vs baseline: 3.8722x; 1.9168x over previous
#include <cuda_runtime.h>
#include <cuda_bf16.h>
#include <math.h>
#include <stdint.h>

// ---------------- problem constants ----------------
#define QL 1024
#define BB 2
#define NH 16
#define DH 64
#define DM 1024
#define DI 4096
#define RL 2048
#define M2 (QL*BB)
#define MR (RL*BB)
#define ATT_SCALE 0.125f

// ================= low-level helpers (baseline PTX, sm_80+) =================
__device__ __forceinline__ uint32_t smem_u32(const void* p) {
    uint32_t a;
    asm("{ .reg .u64 t; cvta.to.shared.u64 t, %1; cvt.u32.u64 %0, t; }" : "=r"(a) : "l"(p));
    return a;
}
__device__ __forceinline__ void cp16(uint32_t dst, const void* src) {
    asm volatile("cp.async.cg.shared.global [%0], [%1], 16;" :: "r"(dst), "l"(src));
}
__device__ __forceinline__ void cp_commit() {
    asm volatile("cp.async.commit_group;" ::: "memory");
}
__device__ __forceinline__ void ldsm4(uint32_t (&r)[4], uint32_t addr) {
    asm volatile("ldmatrix.sync.aligned.m8n8.x4.shared.b16 {%0,%1,%2,%3}, [%4];"
        : "=r"(r[0]), "=r"(r[1]), "=r"(r[2]), "=r"(r[3]) : "r"(addr));
}
__device__ __forceinline__ void mma16816(float (&d)[4], const uint32_t (&a)[4],
                                         uint32_t b0, uint32_t b1) {
    asm volatile("mma.sync.aligned.m16n8k16.row.col.f32.bf16.bf16.f32 "
        "{%0,%1,%2,%3},{%4,%5,%6,%7},{%8,%9},{%0,%1,%2,%3};"
        : "+f"(d[0]), "+f"(d[1]), "+f"(d[2]), "+f"(d[3])
        : "r"(a[0]), "r"(a[1]), "r"(a[2]), "r"(a[3]), "r"(b0), "r"(b1));
}

// ---------------- scratch (static device memory) ----------------
__device__ float g_q   [M2*DM];
__device__ float g_q2  [M2*DM];
__device__ float g_k   [M2*DM];
__device__ float g_v   [M2*DM];
__device__ float g_kr  [MR*DM];
__device__ float g_ef  [M2*NH*2];
__device__ float g_S   [(size_t)BB*NH*QL*QL];   // ac + bk
__device__ float g_BD  [(size_t)BB*NH*QL*RL];   // bd + bkr (windowed)
__device__ float g_attn[M2*DM];
__device__ float g_o   [M2*DM];
__device__ float g_y   [M2*DM];
__device__ float g_t   [M2*DI];
__device__ float g_z   [M2*DM];
__device__ float g_bkT [32*QL];
__device__ float g_bkrT[32*RL];
__device__ float g_penh[(size_t)2*QL*QL];
__device__ float g_peng[(size_t)2*QL*QL];
__device__ float g_diff[(size_t)2*QL*QL];
// bf16 buffers
__device__ __align__(256) __nv_bfloat16 g_Ah [M2*DI];
__device__ __align__(256) __nv_bfloat16 g_Al [M2*DI];
__device__ __align__(256) __nv_bfloat16 g_wqT[2*DM*DM];
__device__ __align__(256) __nv_bfloat16 g_wkT[2*DM*DM];
__device__ __align__(256) __nv_bfloat16 g_wvT[2*DM*DM];
__device__ __align__(256) __nv_bfloat16 g_wrT[2*DM*DM];
__device__ __align__(256) __nv_bfloat16 g_woC[2*DM*DM];
__device__ __align__(256) __nv_bfloat16 g_w1T[2*DM*DI];
__device__ __align__(256) __nv_bfloat16 g_w2T[2*DI*DM];
// head-major attention bf16
__device__ __align__(256) __nv_bfloat16 g_qhh[32*QL*DH], g_qhl[32*QL*DH];
__device__ __align__(256) __nv_bfloat16 g_khh[32*QL*DH], g_khl[32*QL*DH];
__device__ __align__(256) __nv_bfloat16 g_krh[32*RL*DH], g_krl[32*RL*DH];
__device__ __align__(256) __nv_bfloat16 g_vth[32*DH*QL], g_vtl[32*DH*QL];
__device__ __align__(256) __nv_bfloat16 g_Ph [(size_t)32*QL*QL], g_Pl [(size_t)32*QL*QL];

// ================= conversion / repack kernels =================
__global__ void conv_split(const float* __restrict__ X, __nv_bfloat16* __restrict__ hi,
                           __nv_bfloat16* __restrict__ lo, int n4)
{
    int i = blockIdx.x * blockDim.x + threadIdx.x;
    if (i >= n4) return;
    float4 v = ((const float4*)X)[i];
    __nv_bfloat16 hx = __float2bfloat16(v.x), hy = __float2bfloat16(v.y);
    __nv_bfloat16 hz = __float2bfloat16(v.z), hw = __float2bfloat16(v.w);
    ((__nv_bfloat162*)hi)[2*i]   = __nv_bfloat162(hx, hy);
    ((__nv_bfloat162*)hi)[2*i+1] = __nv_bfloat162(hz, hw);
    ((__nv_bfloat162*)lo)[2*i]   = __nv_bfloat162(
        __float2bfloat16(v.x - __bfloat162float(hx)), __float2bfloat16(v.y - __bfloat162float(hy)));
    ((__nv_bfloat162*)lo)[2*i+1] = __nv_bfloat162(
        __float2bfloat16(v.z - __bfloat162float(hz)), __float2bfloat16(v.w - __bfloat162float(hw)));
}

__global__ void convT_split(const float* __restrict__ W, __nv_bfloat16* __restrict__ hi,
                            __nv_bfloat16* __restrict__ lo, int K, int N)
{
    __shared__ float t[32][33];
    int k0 = blockIdx.y * 32, n0 = blockIdx.x * 32;
    int tx = threadIdx.x, ty = threadIdx.y;
#pragma unroll
    for (int p = 0; p < 4; p++)
        t[ty + p*8][tx] = W[(size_t)(k0 + ty + p*8)*N + n0 + tx];
    __syncthreads();
#pragma unroll
    for (int p = 0; p < 4; p++) {
        float v = t[tx][ty + p*8];
        __nv_bfloat16 h = __float2bfloat16(v);
        size_t o = (size_t)(n0 + ty + p*8)*K + k0 + tx;
        hi[o] = h;
        lo[o] = __float2bfloat16(v - __bfloat162float(h));
    }
}

// fp32 [rowsPerB*2][1024] (row=(i*2+b), col=n*64+d) -> bf16 hi/lo [bn][rowsPerB][64]
__global__ void repack_head(const float* __restrict__ X, __nv_bfloat16* __restrict__ hi,
                            __nv_bfloat16* __restrict__ lo, int rowsPerB)
{
    int idx = blockIdx.x * blockDim.x + threadIdx.x;
    int total = 32 * rowsPerB * 16;
    if (idx >= total) return;
    int d4 = idx & 15;
    int rowi = (idx >> 4) % rowsPerB;
    int bn = idx / (16 * rowsPerB);
    int b = bn >> 4, n = bn & 15;
    float4 v = *(const float4*)(X + ((size_t)rowi*2 + b)*DM + n*DH + d4*4);
    size_t o = ((size_t)bn*rowsPerB + rowi)*DH + d4*4;
    __nv_bfloat16 hx = __float2bfloat16(v.x), hy = __float2bfloat16(v.y);
    __nv_bfloat16 hz = __float2bfloat16(v.z), hw = __float2bfloat16(v.w);
    *(__nv_bfloat162*)(hi + o)     = __nv_bfloat162(hx, hy);
    *(__nv_bfloat162*)(hi + o + 2) = __nv_bfloat162(hz, hw);
    *(__nv_bfloat162*)(lo + o)     = __nv_bfloat162(
        __float2bfloat16(v.x - __bfloat162float(hx)), __float2bfloat16(v.y - __bfloat162float(hy)));
    *(__nv_bfloat162*)(lo + o + 2) = __nv_bfloat162(
        __float2bfloat16(v.z - __bfloat162float(hz)), __float2bfloat16(v.w - __bfloat162float(hw)));
}

// v fp32 [(j*2+b)][n*64+d] -> vT bf16 hi/lo [bn][d][j]
__global__ void repack_vT(const float* __restrict__ V, __nv_bfloat16* __restrict__ hi,
                          __nv_bfloat16* __restrict__ lo)
{
    __shared__ float tile[32][33];
    int j0 = blockIdx.x * 32, d0 = blockIdx.y * 32;
    int bn = blockIdx.z, b = bn >> 4, n = bn & 15;
    int tx = threadIdx.x, ty = threadIdx.y;
#pragma unroll
    for (int p = 0; p < 4; p++)
        tile[ty + p*8][tx] = V[((size_t)(j0 + ty + p*8)*2 + b)*DM + n*DH + d0 + tx];
    __syncthreads();
#pragma unroll
    for (int p = 0; p < 4; p++) {
        float v = tile[tx][ty + p*8];
        __nv_bfloat16 h = __float2bfloat16(v);
        size_t o = ((size_t)bn*DH + d0 + ty + p*8)*QL + j0 + tx;
        hi[o] = h;
        lo[o] = __float2bfloat16(v - __bfloat162float(h));
    }
}

// pen[b][i][j] = -1e30*mask[i][j][b]; diff[b][i][j] = seg_mat[i][j][b][1]
__global__ void prep_mask(const float* __restrict__ mask_h, const float* __restrict__ mask_g,
                          const float* __restrict__ seg_mat,
                          float* __restrict__ penh, float* __restrict__ peng,
                          float* __restrict__ diff)
{
    size_t idx = (size_t)blockIdx.x * blockDim.x + threadIdx.x;
    if (idx >= (size_t)2*QL*QL) return;
    int j = idx & 1023;
    int i = (idx >> 10) & 1023;
    int b = idx >> 20;
    size_t src = ((size_t)i*QL + j)*BB + b;
    penh[idx] = -1e30f * mask_h[src];
    peng[idx] = -1e30f * mask_g[src];
    diff[idx] = seg_mat[src*2 + 1];
}

// bias-dot transposed: out[bn][j] = sum_d bias[n*64+d] * X[(j*2+b)*1024 + n*64+d]
__global__ void bias_dotT(const float* __restrict__ X, const float* __restrict__ bias,
                          float* __restrict__ outT, int rowsPerB)
{
    const int gw = (blockIdx.x * blockDim.x + threadIdx.x) >> 5;
    const int lane = threadIdx.x & 31;
    if (gw >= rowsPerB * 2 * NH) return;
    const int row = gw >> 4, n = gw & 15;
    const int j = row >> 1, b = row & 1;
    float s = bias[n*DH + lane]      * X[(size_t)row*DM + n*DH + lane]
            + bias[n*DH + 32 + lane] * X[(size_t)row*DM + n*DH + 32 + lane];
#pragma unroll
    for (int o = 16; o; o >>= 1) s += __shfl_xor_sync(0xffffffffu, s, o);
    if (!lane) outT[(size_t)(b*16 + n)*rowsPerB + j] = s;
}

// ================= split-bf16 dense GEMM (proven in R3) =================
#define GSTAGE 65536
#define GSMEM_BYTES (2*GSTAGE)

__device__ __forceinline__ void g_load_stage(
    const __nv_bfloat16* __restrict__ Ah, const __nv_bfloat16* __restrict__ Al,
    const __nv_bfloat16* __restrict__ Bh, const __nv_bfloat16* __restrict__ Bl,
    uint32_t st, int m0, int n0, int K, int kc, int tid)
{
    const size_t ko = (size_t)kc * 64;
#pragma unroll
    for (int p = 0; p < 4; p++) {
        int c = p*256 + tid;
        int row = c >> 3, kcol = c & 7;
        uint32_t sw = (uint32_t)(row*128 + kcol*16) ^ ((row & 7) << 4);
        const size_t ga = (size_t)(m0 + row)*K + ko + kcol*8;
        const size_t gb = (size_t)(n0 + row)*K + ko + kcol*8;
        cp16(st + sw,         Ah + ga);
        cp16(st + 16384 + sw, Al + ga);
        cp16(st + 32768 + sw, Bh + gb);
        cp16(st + 49152 + sw, Bl + gb);
    }
    cp_commit();
}

template<int EPI>
__global__ void __launch_bounds__(256, 1) gemm_mma(
    const __nv_bfloat16* __restrict__ Ah, const __nv_bfloat16* __restrict__ Al,
    const __nv_bfloat16* __restrict__ Bh, const __nv_bfloat16* __restrict__ Bl,
    const float* __restrict__ bias, float* __restrict__ C, int K, int ldc)
{
    extern __shared__ char dsm[];
    const uint32_t sbase = smem_u32(dsm);
    const int tid = threadIdx.x, lane = tid & 31, warp = tid >> 5;
    const int m0 = blockIdx.y * 128, n0 = blockIdx.x * 128;
    const int wm = (warp & 1) * 64, wn = (warp >> 1) * 32;
    const int NC = K >> 6;

    float acc[4][4][4] = {};
    g_load_stage(Ah, Al, Bh, Bl, sbase,          m0, n0, K, 0, tid);
    g_load_stage(Ah, Al, Bh, Bl, sbase + GSTAGE, m0, n0, K, 1, tid);
    asm volatile("cp.async.wait_group 1;" ::: "memory");
    __syncthreads();

    const int arow = wm + (lane & 15);
    const int akb  = (lane & 16);
    const int brow = wn + ((lane & 16) >> 1) + (lane & 7);
    const int bkb  = ((lane & 8) << 1);

    for (int kc = 0; kc < NC; kc++) {
        const uint32_t st = sbase + (kc & 1) * GSTAGE;
#pragma unroll
        for (int ks = 0; ks < 4; ks++) {
            const int kb = ks*32;
            uint32_t ah[4][4], al[4][4], bh[2][4], bl[2][4];
#pragma unroll
            for (int im = 0; im < 4; im++) {
                int row = arow + im*16;
                uint32_t off = (uint32_t)(row*128 + kb + akb) ^ ((row & 7) << 4);
                ldsm4(ah[im], st + off);
                ldsm4(al[im], st + 16384 + off);
            }
#pragma unroll
            for (int np = 0; np < 2; np++) {
                int row = brow + np*16;
                uint32_t off = (uint32_t)(row*128 + kb + bkb) ^ ((row & 7) << 4);
                ldsm4(bh[np], st + 32768 + off);
                ldsm4(bl[np], st + 49152 + off);
            }
#pragma unroll
            for (int im = 0; im < 4; im++)
#pragma unroll
                for (int in = 0; in < 4; in++) {
                    const int np = in >> 1, hf = (in & 1) * 2;
                    mma16816(acc[im][in], ah[im], bh[np][hf], bh[np][hf+1]);
                    mma16816(acc[im][in], ah[im], bl[np][hf], bl[np][hf+1]);
                    mma16816(acc[im][in], al[im], bh[np][hf], bh[np][hf+1]);
                }
        }
        __syncthreads();
        if (kc + 2 < NC) {
            g_load_stage(Ah, Al, Bh, Bl, sbase + (kc & 1)*GSTAGE, m0, n0, K, kc + 2, tid);
            asm volatile("cp.async.wait_group 1;" ::: "memory");
        } else {
            asm volatile("cp.async.wait_group 0;" ::: "memory");
        }
        __syncthreads();
    }

    const int rbase = m0 + wm + (lane >> 2);
    const int cbase = n0 + wn + 2*(lane & 3);
#pragma unroll
    for (int im = 0; im < 4; im++) {
#pragma unroll
        for (int in = 0; in < 4; in++) {
            int col = cbase + in*8;
            float v0 = acc[im][in][0], v1 = acc[im][in][1];
            float v2 = acc[im][in][2], v3 = acc[im][in][3];
            if (EPI >= 1) {
                float b0 = bias[col], b1 = bias[col+1];
                v0 += b0; v1 += b1; v2 += b0; v3 += b1;
            }
            if (EPI == 2) {
                v0 = 0.5f*v0*(1.0f + erff(v0*0.7071067811865476f));
                v1 = 0.5f*v1*(1.0f + erff(v1*0.7071067811865476f));
                v2 = 0.5f*v2*(1.0f + erff(v2*0.7071067811865476f));
                v3 = 0.5f*v3*(1.0f + erff(v3*0.7071067811865476f));
            }
            int r0 = rbase + im*16, r1 = r0 + 8;
            *(float2*)(C + (size_t)r0*ldc + col) = make_float2(v0, v1);
            *(float2*)(C + (size_t)r1*ldc + col) = make_float2(v2, v3);
        }
    }
}

// ================= batched score GEMM (split-bf16 mma, K=64) =================
// C[bn][i][j(+off)] = Q[bn][i][:] . K[bn][j][:]  + biasT[bn][j]
// window=1: only the 9 jr-tiles the rel_shift gather touches (ct = 7 - it + bx).
#define SC_SMEM 65536

__global__ void __launch_bounds__(256, 1) score_mma(
    const __nv_bfloat16* __restrict__ Qh, const __nv_bfloat16* __restrict__ Ql,
    const __nv_bfloat16* __restrict__ Kh, const __nv_bfloat16* __restrict__ Kl,
    const float* __restrict__ biasT, float* __restrict__ C, int Ncols, int window)
{
    extern __shared__ char dsm[];
    const uint32_t st = smem_u32(dsm);
    const int tid = threadIdx.x, lane = tid & 31, warp = tid >> 5;
    const int bn = blockIdx.z;
    const int i0 = blockIdx.y * 128;
    int ct = window ? (7 - (int)blockIdx.y + (int)blockIdx.x) : (int)blockIdx.x;
    const int j0 = ct * 128;

    const size_t qb = ((size_t)bn*QL + i0)*DH;
    const size_t kb = ((size_t)bn*Ncols + j0)*DH;
#pragma unroll
    for (int p = 0; p < 4; p++) {
        int c = p*256 + tid;
        int row = c >> 3, kcol = c & 7;
        uint32_t sw = (uint32_t)(row*128 + kcol*16) ^ ((row & 7) << 4);
        cp16(st + sw,         Qh + qb + (size_t)row*DH + kcol*8);
        cp16(st + 16384 + sw, Ql + qb + (size_t)row*DH + kcol*8);
        cp16(st + 32768 + sw, Kh + kb + (size_t)row*DH + kcol*8);
        cp16(st + 49152 + sw, Kl + kb + (size_t)row*DH + kcol*8);
    }
    cp_commit();
    asm volatile("cp.async.wait_group 0;" ::: "memory");
    __syncthreads();

    const int wm = (warp & 1) * 64, wn = (warp >> 1) * 32;
    const int arow = wm + (lane & 15);
    const int akb  = (lane & 16);
    const int brow = wn + ((lane & 16) >> 1) + (lane & 7);
    const int bkb  = ((lane & 8) << 1);

    float acc[4][4][4] = {};
#pragma unroll
    for (int ks = 0; ks < 4; ks++) {
        const int kbyte = ks*32;
        uint32_t ah[4][4], al[4][4], bh[2][4], bl[2][4];
#pragma unroll
        for (int im = 0; im < 4; im++) {
            int row = arow + im*16;
            uint32_t off = (uint32_t)(row*128 + kbyte + akb) ^ ((row & 7) << 4);
            ldsm4(ah[im], st + off);
            ldsm4(al[im], st + 16384 + off);
        }
#pragma unroll
        for (int np = 0; np < 2; np++) {
            int row = brow + np*16;
            uint32_t off = (uint32_t)(row*128 + kbyte + bkb) ^ ((row & 7) << 4);
            ldsm4(bh[np], st + 32768 + off);
            ldsm4(bl[np], st + 49152 + off);
        }
#pragma unroll
        for (int im = 0; im < 4; im++)
#pragma unroll
            for (int in = 0; in < 4; in++) {
                const int np = in >> 1, hf = (in & 1) * 2;
                mma16816(acc[im][in], ah[im], bh[np][hf], bh[np][hf+1]);
                mma16816(acc[im][in], ah[im], bl[np][hf], bl[np][hf+1]);
                mma16816(acc[im][in], al[im], bh[np][hf], bh[np][hf+1]);
            }
    }

    float* Cb = C + (size_t)bn*QL*Ncols;
    const float* bt = biasT + (size_t)bn*Ncols;
    const int rbase = i0 + wm + (lane >> 2);
    const int cbase = j0 + wn + 2*(lane & 3);
#pragma unroll
    for (int im = 0; im < 4; im++)
#pragma unroll
        for (int in = 0; in < 4; in++) {
            int col = cbase + in*8;
            float b0 = bt[col], b1 = bt[col+1];
            int r0 = rbase + im*16, r1 = r0 + 8;
            *(float2*)(Cb + (size_t)r0*Ncols + col) =
                make_float2(acc[im][in][0] + b0, acc[im][in][1] + b1);
            *(float2*)(Cb + (size_t)r1*Ncols + col) =
                make_float2(acc[im][in][2] + b0, acc[im][in][3] + b1);
        }
}

// ================= fused combine + softmax + bf16-split P =================
__global__ void __launch_bounds__(256) softmax_fused(
    const float* __restrict__ S, const float* __restrict__ BD,
    const float* __restrict__ pen, const float* __restrict__ diff,
    const float* __restrict__ ef,
    __nv_bfloat16* __restrict__ Ph, __nv_bfloat16* __restrict__ Pl)
{
    __shared__ float red[8];
    const int i = blockIdx.x, bn = blockIdx.y, b = bn >> 4, n = bn & 15;
    const int t = threadIdx.x, lane = t & 31, w = t >> 5;
    const float* Sr = S    + ((size_t)bn << 20) + ((size_t)i << 10);
    const float* Br = BD   + ((size_t)bn << 21) + ((size_t)i << 11) + (QL - i);
    const float* Pr = pen  + ((size_t)b  << 20) + ((size_t)i << 10);
    const float* Dr = diff + ((size_t)b  << 20) + ((size_t)i << 10);
    const float e0 = ef[(((size_t)i*2 + b)*NH + n)*2];
    const float de = ef[(((size_t)i*2 + b)*NH + n)*2 + 1] - e0;

    float v[4];
#pragma unroll
    for (int p = 0; p < 4; p++) {
        int j = t + p*256;
        v[p] = (Sr[j] + Br[j] + e0 + de*Dr[j]) * ATT_SCALE + Pr[j];
    }
    float m = fmaxf(fmaxf(v[0], v[1]), fmaxf(v[2], v[3]));
#pragma unroll
    for (int o = 16; o; o >>= 1) m = fmaxf(m, __shfl_xor_sync(0xffffffffu, m, o));
    if (!lane) red[w] = m;
    __syncthreads();
    m = red[lane & 7];
#pragma unroll
    for (int o = 4; o; o >>= 1) m = fmaxf(m, __shfl_xor_sync(0xffffffffu, m, o));
    float sum = 0.f;
#pragma unroll
    for (int p = 0; p < 4; p++) { v[p] = expf(v[p] - m); sum += v[p]; }
#pragma unroll
    for (int o = 16; o; o >>= 1) sum += __shfl_xor_sync(0xffffffffu, sum, o);
    __syncthreads();
    if (!lane) red[w] = sum;
    __syncthreads();
    sum = red[lane & 7];
#pragma unroll
    for (int o = 4; o; o >>= 1) sum += __shfl_xor_sync(0xffffffffu, sum, o);
    const float inv = 1.0f / sum;
    const size_t base = ((size_t)bn << 20) + ((size_t)i << 10);
#pragma unroll
    for (int p = 0; p < 4; p++) {
        int j = t + p*256;
        float pv = v[p] * inv;
        __nv_bfloat16 ph = __float2bfloat16(pv);
        Ph[base + j] = ph;
        Pl[base + j] = __float2bfloat16(pv - __bfloat162float(ph));
    }
}

// ================= batched PV GEMM (split-bf16 mma, M=128 N=64 K=1024) =================
#define PV_STAGE 49152
#define PV_SMEM (2*PV_STAGE)

__device__ __forceinline__ void pv_load(
    const __nv_bfloat16* __restrict__ Ph, const __nv_bfloat16* __restrict__ Pl,
    const __nv_bfloat16* __restrict__ Vh, const __nv_bfloat16* __restrict__ Vl,
    uint32_t st, size_t pbase, size_t vbase, int kc, int tid)
{
    const size_t ko = (size_t)kc * 64;
#pragma unroll
    for (int p = 0; p < 4; p++) {
        int c = p*256 + tid;
        int row = c >> 3, kcol = c & 7;
        uint32_t sw = (uint32_t)(row*128 + kcol*16) ^ ((row & 7) << 4);
        cp16(st + sw,         Ph + pbase + (size_t)row*QL + ko + kcol*8);
        cp16(st + 16384 + sw, Pl + pbase + (size_t)row*QL + ko + kcol*8);
    }
#pragma unroll
    for (int p = 0; p < 2; p++) {
        int c = p*256 + tid;
        int row = c >> 3, kcol = c & 7;   // row 0..63
        uint32_t sw = (uint32_t)(row*128 + kcol*16) ^ ((row & 7) << 4);
        cp16(st + 32768 + sw, Vh + vbase + (size_t)row*QL + ko + kcol*8);
        cp16(st + 40960 + sw, Vl + vbase + (size_t)row*QL + ko + kcol*8);
    }
    cp_commit();
}

__global__ void __launch_bounds__(256, 1) pv_mma(
    const __nv_bfloat16* __restrict__ Ph, const __nv_bfloat16* __restrict__ Pl,
    const __nv_bfloat16* __restrict__ Vh, const __nv_bfloat16* __restrict__ Vl,
    float* __restrict__ O)
{
    extern __shared__ char dsm[];
    const uint32_t sbase = smem_u32(dsm);
    const int tid = threadIdx.x, lane = tid & 31, warp = tid >> 5;
    const int bn = blockIdx.y, b = bn >> 4, n = bn & 15;
    const int i0 = blockIdx.x * 128;
    const size_t pbase = ((size_t)bn << 20) + (size_t)i0*QL;
    const size_t vbase = (size_t)bn * DH * QL;

    float acc[2][4][4] = {};
    pv_load(Ph, Pl, Vh, Vl, sbase,            pbase, vbase, 0, tid);
    pv_load(Ph, Pl, Vh, Vl, sbase + PV_STAGE, pbase, vbase, 1, tid);
    asm volatile("cp.async.wait_group 1;" ::: "memory");
    __syncthreads();

    const int wm = (warp & 3) * 32, wn = (warp >> 2) * 32;
    const int arow = wm + (lane & 15);
    const int akb  = (lane & 16);
    const int brow = wn + ((lane & 16) >> 1) + (lane & 7);
    const int bkb  = ((lane & 8) << 1);

    for (int kc = 0; kc < 16; kc++) {
        const uint32_t st = sbase + (kc & 1) * PV_STAGE;
#pragma unroll
        for (int ks = 0; ks < 4; ks++) {
            const int kb = ks*32;
            uint32_t ah[2][4], al[2][4], bh[2][4], bl[2][4];
#pragma unroll
            for (int im = 0; im < 2; im++) {
                int row = arow + im*16;
                uint32_t off = (uint32_t)(row*128 + kb + akb) ^ ((row & 7) << 4);
                ldsm4(ah[im], st + off);
                ldsm4(al[im], st + 16384 + off);
            }
#pragma unroll
            for (int np = 0; np < 2; np++) {
                int row = brow + np*16;
                uint32_t off = (uint32_t)(row*128 + kb + bkb) ^ ((row & 7) << 4);
                ldsm4(bh[np], st + 32768 + off);
                ldsm4(bl[np], st + 40960 + off);
            }
#pragma unroll
            for (int im = 0; im < 2; im++)
#pragma unroll
                for (int in = 0; in < 4; in++) {
                    const int np = in >> 1, hf = (in & 1) * 2;
                    mma16816(acc[im][in], ah[im], bh[np][hf], bh[np][hf+1]);
                    mma16816(acc[im][in], ah[im], bl[np][hf], bl[np][hf+1]);
                    mma16816(acc[im][in], al[im], bh[np][hf], bh[np][hf+1]);
                }
        }
        __syncthreads();
        if (kc + 2 < 16) {
            pv_load(Ph, Pl, Vh, Vl, sbase + (kc & 1)*PV_STAGE, pbase, vbase, kc + 2, tid);
            asm volatile("cp.async.wait_group 1;" ::: "memory");
        } else {
            asm volatile("cp.async.wait_group 0;" ::: "memory");
        }
        __syncthreads();
    }

    const int rl = wm + (lane >> 2);
    const int cb = wn + 2*(lane & 3);
#pragma unroll
    for (int im = 0; im < 2; im++)
#pragma unroll
        for (int in = 0; in < 4; in++) {
            int col = cb + in*8;
            int r0 = i0 + rl + im*16, r1 = r0 + 8;
            *(float2*)(O + ((size_t)r0*2 + b)*DM + n*DH + col) =
                make_float2(acc[im][in][0], acc[im][in][1]);
            *(float2*)(O + ((size_t)r1*2 + b)*DM + n*DH + col) =
                make_float2(acc[im][in][2], acc[im][in][3]);
        }
}

// ================= small fp32 kernels =================
__global__ void ef_kernel(const float* __restrict__ q, const float* __restrict__ rsb,
                          const float* __restrict__ se, float* __restrict__ ef)
{
    const int gw = (blockIdx.x * blockDim.x + threadIdx.x) >> 5;
    const int lane = threadIdx.x & 31;
    if (gw >= M2 * NH) return;
    const int row = gw >> 4, n = gw & 15;
    const float v0 = q[(size_t)row*DM + n*DH + lane]      + rsb[n*DH + lane];
    const float v1 = q[(size_t)row*DM + n*DH + 32 + lane] + rsb[n*DH + 32 + lane];
    float s0 = v0*se[n*DH + lane] + v1*se[n*DH + 32 + lane];
    float s1 = v0*se[NH*DH + n*DH + lane] + v1*se[NH*DH + n*DH + 32 + lane];
#pragma unroll
    for (int o = 16; o; o >>= 1) {
        s0 += __shfl_xor_sync(0xffffffffu, s0, o);
        s1 += __shfl_xor_sync(0xffffffffu, s1, o);
    }
    if (!lane) { ef[gw*2] = s0; ef[gw*2 + 1] = s1; }
}

__global__ void __launch_bounds__(256) add_ln(
    const float* __restrict__ a, const float* __restrict__ x,
    const float* __restrict__ gamma, const float* __restrict__ beta,
    float* __restrict__ out)
{
    __shared__ float buf[1024];
    __shared__ float red[8];
    __shared__ float s_stat;
    const size_t base = (size_t)blockIdx.x << 10;
    const int t = threadIdx.x, lane = t & 31, w = t >> 5;
    float sum = 0.f;
#pragma unroll
    for (int p = 0; p < 4; p++) {
        float v = a[base + t + p*256] + x[base + t + p*256];
        buf[t + p*256] = v; sum += v;
    }
#pragma unroll
    for (int o = 16; o; o >>= 1) sum += __shfl_xor_sync(0xffffffffu, sum, o);
    if (!lane) red[w] = sum;
    __syncthreads();
    if (t == 0) { float s = 0; for (int i = 0; i < 8; i++) s += red[i]; s_stat = s * (1.0f/1024.0f); }
    __syncthreads();
    const float mean = s_stat;
    float vs = 0.f;
#pragma unroll
    for (int p = 0; p < 4; p++) { float d = buf[t + p*256] - mean; vs += d*d; }
#pragma unroll
    for (int o = 16; o; o >>= 1) vs += __shfl_xor_sync(0xffffffffu, vs, o);
    __syncthreads();
    if (!lane) red[w] = vs;
    __syncthreads();
    if (t == 0) { float s = 0; for (int i = 0; i < 8; i++) s += red[i]; s_stat = s * (1.0f/1024.0f); }
    __syncthreads();
    const float r = rsqrtf(s_stat + 1e-12f);
#pragma unroll
    for (int p = 0; p < 4; p++) {
        int c = t + p*256;
        out[base + c] = (buf[c] - mean) * r * gamma[c] + beta[c];
    }
}

// ================= host orchestration =================
static void conv(const float* x, __nv_bfloat16* hi, __nv_bfloat16* lo, size_t n)
{
    int n4 = (int)(n / 4);
    conv_split<<<(n4 + 255)/256, 256>>>(x, hi, lo, n4);
}

static void gemm(int epi, const __nv_bfloat16* Ah, const __nv_bfloat16* Al,
                 const __nv_bfloat16* Bpair, const float* bias, float* C,
                 int M, int N, int K)
{
    const __nv_bfloat16* Bh = Bpair;
    const __nv_bfloat16* Bl = Bpair + (size_t)N*K;
    dim3 gr(N/128, M/128);
    if (epi == 0)      gemm_mma<0><<<gr, 256, GSMEM_BYTES>>>(Ah, Al, Bh, Bl, bias, C, K, N);
    else if (epi == 1) gemm_mma<1><<<gr, 256, GSMEM_BYTES>>>(Ah, Al, Bh, Bl, bias, C, K, N);
    else               gemm_mma<2><<<gr, 256, GSMEM_BYTES>>>(Ah, Al, Bh, Bl, bias, C, K, N);
}

extern "C" void kernel_launch(void* const* d_in, const int* in_sizes, int n_in,
                              void* d_out, int out_size)
{
    (void)in_sizes; (void)n_in; (void)out_size;
    const float* h       = (const float*)d_in[0];
    const float* g       = (const float*)d_in[1];
    const float* r       = (const float*)d_in[2];
    const float* mask_h  = (const float*)d_in[3];
    const float* mask_g  = (const float*)d_in[4];
    const float* seg_mat = (const float*)d_in[5];
    const float* wq      = (const float*)d_in[6];
    const float* wk      = (const float*)d_in[7];
    const float* wv      = (const float*)d_in[8];
    const float* wo      = (const float*)d_in[9];
    const float* wr      = (const float*)d_in[10];
    const float* rwb     = (const float*)d_in[11];
    const float* rrb     = (const float*)d_in[12];
    const float* rsb     = (const float*)d_in[13];
    const float* se      = (const float*)d_in[14];
    const float* lnga    = (const float*)d_in[15];
    const float* lnba    = (const float*)d_in[16];
    const float* w1      = (const float*)d_in[17];
    const float* b1      = (const float*)d_in[18];
    const float* w2      = (const float*)d_in[19];
    const float* b2      = (const float*)d_in[20];
    const float* lngf    = (const float*)d_in[21];
    const float* lnbf    = (const float*)d_in[22];

    cudaFuncSetAttribute(gemm_mma<0>, cudaFuncAttributeMaxDynamicSharedMemorySize, GSMEM_BYTES);
    cudaFuncSetAttribute(gemm_mma<1>, cudaFuncAttributeMaxDynamicSharedMemorySize, GSMEM_BYTES);
    cudaFuncSetAttribute(gemm_mma<2>, cudaFuncAttributeMaxDynamicSharedMemorySize, GSMEM_BYTES);
    cudaFuncSetAttribute(score_mma,   cudaFuncAttributeMaxDynamicSharedMemorySize, SC_SMEM);
    cudaFuncSetAttribute(pv_mma,      cudaFuncAttributeMaxDynamicSharedMemorySize, PV_SMEM);

    float *q,*q2,*k,*v,*kr,*ef,*S,*BD,*attn,*o,*y,*t,*z,*bkT,*bkrT,*penh,*peng,*diff;
    __nv_bfloat16 *Ah,*Al,*wqT,*wkT,*wvT,*wrT,*woC,*w1T,*w2T;
    __nv_bfloat16 *qhh,*qhl,*khh,*khl,*krh,*krl,*vth,*vtl,*Ph,*Pl;
    cudaGetSymbolAddress((void**)&q,    g_q);
    cudaGetSymbolAddress((void**)&q2,   g_q2);
    cudaGetSymbolAddress((void**)&k,    g_k);
    cudaGetSymbolAddress((void**)&v,    g_v);
    cudaGetSymbolAddress((void**)&kr,   g_kr);
    cudaGetSymbolAddress((void**)&ef,   g_ef);
    cudaGetSymbolAddress((void**)&S,    g_S);
    cudaGetSymbolAddress((void**)&BD,   g_BD);
    cudaGetSymbolAddress((void**)&attn, g_attn);
    cudaGetSymbolAddress((void**)&o,    g_o);
    cudaGetSymbolAddress((void**)&y,    g_y);
    cudaGetSymbolAddress((void**)&t,    g_t);
    cudaGetSymbolAddress((void**)&z,    g_z);
    cudaGetSymbolAddress((void**)&bkT,  g_bkT);
    cudaGetSymbolAddress((void**)&bkrT, g_bkrT);
    cudaGetSymbolAddress((void**)&penh, g_penh);
    cudaGetSymbolAddress((void**)&peng, g_peng);
    cudaGetSymbolAddress((void**)&diff, g_diff);
    cudaGetSymbolAddress((void**)&Ah,   g_Ah);
    cudaGetSymbolAddress((void**)&Al,   g_Al);
    cudaGetSymbolAddress((void**)&wqT,  g_wqT);
    cudaGetSymbolAddress((void**)&wkT,  g_wkT);
    cudaGetSymbolAddress((void**)&wvT,  g_wvT);
    cudaGetSymbolAddress((void**)&wrT,  g_wrT);
    cudaGetSymbolAddress((void**)&woC,  g_woC);
    cudaGetSymbolAddress((void**)&w1T,  g_w1T);
    cudaGetSymbolAddress((void**)&w2T,  g_w2T);
    cudaGetSymbolAddress((void**)&qhh,  g_qhh);
    cudaGetSymbolAddress((void**)&qhl,  g_qhl);
    cudaGetSymbolAddress((void**)&khh,  g_khh);
    cudaGetSymbolAddress((void**)&khl,  g_khl);
    cudaGetSymbolAddress((void**)&krh,  g_krh);
    cudaGetSymbolAddress((void**)&krl,  g_krl);
    cudaGetSymbolAddress((void**)&vth,  g_vth);
    cudaGetSymbolAddress((void**)&vtl,  g_vtl);
    cudaGetSymbolAddress((void**)&Ph,   g_Ph);
    cudaGetSymbolAddress((void**)&Pl,   g_Pl);

    // ---- weight prep ----
    dim3 tb(32, 8);
    convT_split<<<dim3(DM/32, DM/32), tb>>>(wq, wqT, wqT + (size_t)DM*DM, DM, DM);
    convT_split<<<dim3(DM/32, DM/32), tb>>>(wk, wkT, wkT + (size_t)DM*DM, DM, DM);
    convT_split<<<dim3(DM/32, DM/32), tb>>>(wv, wvT, wvT + (size_t)DM*DM, DM, DM);
    convT_split<<<dim3(DM/32, DM/32), tb>>>(wr, wrT, wrT + (size_t)DM*DM, DM, DM);
    conv(wo, woC, woC + (size_t)DM*DM, (size_t)DM*DM);
    convT_split<<<dim3(DI/32, DM/32), tb>>>(w1, w1T, w1T + (size_t)DM*DI, DM, DI);
    convT_split<<<dim3(DM/32, DI/32), tb>>>(w2, w2T, w2T + (size_t)DI*DM, DI, DM);
    prep_mask<<<(2*QL*QL + 255)/256, 256>>>(mask_h, mask_g, seg_mat, penh, peng, diff);

    // ---- shared projections ----
    conv(h, Ah, Al, (size_t)M2*DM);
    gemm(0, Ah, Al, wkT, nullptr, k,  M2, DM, DM);
    gemm(0, Ah, Al, wvT, nullptr, v,  M2, DM, DM);
    gemm(0, Ah, Al, wqT, nullptr, q,  M2, DM, DM);
    conv(r, Ah, Al, (size_t)MR*DM);
    gemm(0, Ah, Al, wrT, nullptr, kr, MR, DM, DM);
    conv(g, Ah, Al, (size_t)M2*DM);
    gemm(0, Ah, Al, wqT, nullptr, q2, M2, DM, DM);

    bias_dotT<<<(M2*NH*32 + 255)/256, 256>>>(k,  rwb, bkT,  QL);
    bias_dotT<<<(MR*NH*32 + 255)/256, 256>>>(kr, rrb, bkrT, RL);
    repack_head<<<(32*QL*16 + 255)/256, 256>>>(k,  khh, khl, QL);
    repack_head<<<(32*RL*16 + 255)/256, 256>>>(kr, krh, krl, RL);
    repack_vT<<<dim3(QL/32, DH/32, 32), tb>>>(v, vth, vtl);

    float* out_h = (float*)d_out;
    float* out_g = out_h + (size_t)M2*DM;

    // ---- two streams ----
    for (int s = 0; s < 2; s++) {
        const float* x    = s ? g : h;
        const float* pen  = s ? peng : penh;
        const float* qs   = s ? q2 : q;
        float* outp       = s ? out_g : out_h;

        ef_kernel<<<(M2*NH*32 + 255)/256, 256>>>(qs, rsb, se, ef);
        repack_head<<<(32*QL*16 + 255)/256, 256>>>(qs, qhh, qhl, QL);
        score_mma<<<dim3(8, 8, 32), 256, SC_SMEM>>>(qhh, qhl, khh, khl, bkT,  S,  QL, 0);
        score_mma<<<dim3(9, 8, 32), 256, SC_SMEM>>>(qhh, qhl, krh, krl, bkrT, BD, RL, 1);
        softmax_fused<<<dim3(QL, 32), 256>>>(S, BD, pen, diff, ef, Ph, Pl);
        pv_mma<<<dim3(8, 32), 256, PV_SMEM>>>(Ph, Pl, vth, vtl, attn);

        conv(attn, Ah, Al, (size_t)M2*DM);
        gemm(0, Ah, Al, woC, nullptr, o, M2, DM, DM);
        add_ln<<<M2, 256>>>(o, x, lnga, lnba, y);

        conv(y, Ah, Al, (size_t)M2*DM);
        gemm(2, Ah, Al, w1T, b1, t, M2, DI, DM);
        conv(t, Ah, Al, (size_t)M2*DI);
        gemm(1, Ah, Al, w2T, b2, z, M2, DM, DI);
        add_ln<<<M2, 256>>>(z, y, lngf, lnbf, outp);
    }
}